// round 1
// baseline (speedup 1.0000x reference)
#include <cuda_runtime.h>

// Problem constants
constexpr int Bc = 2, Sc = 2048, Dc = 1024, Hc = 16, DHc = 64;
constexpr int Mc = Bc * Sc;        // 4096
constexpr int NQKV = 3 * Dc;       // 3072

// Scratch (device globals; no allocation allowed)
__device__ float g_qkv[Mc * NQKV];   // [4096, 3072]
__device__ float g_ctx[Mc * Dc];     // [4096, 1024] context before final proj

// ---------------------------------------------------------------------------
// SGEMM + bias: C[M,N] = A[M,K] @ W[K,N] + bias[N]
// BM=128, BN=64, BK=16, 256 threads, 8x4 per-thread microtile. fp32.
// All dims here are multiples of the tile sizes (4096/3072/1024).
// ---------------------------------------------------------------------------
__global__ __launch_bounds__(256) void sgemm_bias_kernel(
    const float* __restrict__ A, const float* __restrict__ W,
    const float* __restrict__ bias, float* __restrict__ C,
    int M, int N, int K)
{
    constexpr int BM = 128, BN = 64, BK = 16;
    constexpr int ASTR = 132;  // padded stride (multiple of 4 for float4 align)
    __shared__ __align__(16) float As[BK][ASTR];
    __shared__ __align__(16) float Bs[BK][BN];

    const int tid = threadIdx.x;
    const int m0 = blockIdx.y * BM;
    const int n0 = blockIdx.x * BN;
    const int r0 = (tid >> 4) * 8;   // 0..120 step 8
    const int c0 = (tid & 15) * 4;   // 0..60 step 4

    float acc[8][4];
#pragma unroll
    for (int i = 0; i < 8; i++)
#pragma unroll
        for (int j = 0; j < 4; j++) acc[i][j] = 0.f;

    for (int kb = 0; kb < K; kb += BK) {
        // Load A tile: 128x16 = 512 float4, 2 per thread. Store transposed.
#pragma unroll
        for (int jj = 0; jj < 2; jj++) {
            int id  = tid + jj * 256;
            int row = id >> 2;
            int kq  = (id & 3) * 4;
            float4 v = *(const float4*)(A + (size_t)(m0 + row) * K + kb + kq);
            As[kq + 0][row] = v.x;
            As[kq + 1][row] = v.y;
            As[kq + 2][row] = v.z;
            As[kq + 3][row] = v.w;
        }
        // Load B tile: 16x64 = 256 float4, 1 per thread
        {
            int row = tid >> 4;
            int cq  = (tid & 15) * 4;
            float4 v = *(const float4*)(W + (size_t)(kb + row) * N + n0 + cq);
            *(float4*)&Bs[row][cq] = v;
        }
        __syncthreads();

#pragma unroll
        for (int k = 0; k < BK; k++) {
            float4 a0 = *(float4*)&As[k][r0];
            float4 a1 = *(float4*)&As[k][r0 + 4];
            float4 bv = *(float4*)&Bs[k][c0];
            float a[8] = {a0.x, a0.y, a0.z, a0.w, a1.x, a1.y, a1.z, a1.w};
            float bb[4] = {bv.x, bv.y, bv.z, bv.w};
#pragma unroll
            for (int i = 0; i < 8; i++)
#pragma unroll
                for (int j = 0; j < 4; j++)
                    acc[i][j] += a[i] * bb[j];
        }
        __syncthreads();
    }

    float4 bv = *(const float4*)(bias + n0 + c0);
    float bb[4] = {bv.x, bv.y, bv.z, bv.w};
#pragma unroll
    for (int i = 0; i < 8; i++) {
        float4 o;
        o.x = acc[i][0] + bb[0];
        o.y = acc[i][1] + bb[1];
        o.z = acc[i][2] + bb[2];
        o.w = acc[i][3] + bb[3];
        *(float4*)(C + (size_t)(m0 + r0 + i) * N + n0 + c0) = o;
    }
}

// ---------------------------------------------------------------------------
// Fused attention: per (b, h, 16-row q tile):
//   scores (exact max-subtracted softmax over full 2048-row, staged in smem),
//   writes normalized attn_prob [B,H,S,S], accumulates context -> g_ctx.
// 256 threads: thread = (r = tid>>4 in 0..15 q-row, lane = tid&15).
// ---------------------------------------------------------------------------
constexpr int PSTR = 2064;  // probs smem row stride (x16 banks offset per row)
constexpr int KVSTR = 68;   // K/V tile stride

constexpr int ATTN_SMEM_FLOATS = 16 * PSTR + 16 * 64 + 2 * 64 * KVSTR;
constexpr int ATTN_SMEM_BYTES  = ATTN_SMEM_FLOATS * 4;  // 171,008 B

__global__ __launch_bounds__(256) void attn_kernel(
    const float* __restrict__ qkv, const float* __restrict__ mask,
    float* __restrict__ ctx_out, float* __restrict__ attn_out)
{
    extern __shared__ __align__(16) float sm[];
    float* probs = sm;                       // [16][PSTR]
    float* Qs    = probs + 16 * PSTR;        // [16][64]
    float* Ks    = Qs + 16 * 64;             // [64][KVSTR]
    float* Vs    = Ks + 64 * KVSTR;          // [64][KVSTR]
    __shared__ float s_inv[16];

    const int tid  = threadIdx.x;
    const int r    = tid >> 4;
    const int lane = tid & 15;
    const int q0   = blockIdx.x * 16;
    const int h    = blockIdx.y;
    const int b    = blockIdx.z;

    const float* qbase = qkv + (size_t)b * Sc * NQKV;

    // Load Q tile [16 x 64]
    {
        float4 v = *(const float4*)(qbase + (size_t)(q0 + r) * NQKV + h * 64 + lane * 4);
        *(float4*)&Qs[r * 64 + lane * 4] = v;
    }
    const float* mrow = mask + (size_t)b * Sc * Sc + (size_t)(q0 + r) * Sc;

    // ---- Pass 1: scores -> probs smem (raw, scaled + mask), track row max ----
    float maxv = -3.0e38f;
    for (int kb = 0; kb < Sc; kb += 64) {
        __syncthreads();
#pragma unroll
        for (int jj = 0; jj < 4; jj++) {
            int id  = tid + jj * 256;
            int row = id >> 4;
            int dq  = (id & 15) * 4;
            float4 v = *(const float4*)(qbase + (size_t)(kb + row) * NQKV + Dc + h * 64 + dq);
            *(float4*)&Ks[row * KVSTR + dq] = v;
        }
        __syncthreads();

        float a0 = 0.f, a1 = 0.f, a2 = 0.f, a3 = 0.f;
#pragma unroll
        for (int d4 = 0; d4 < 16; d4++) {
            float4 q4 = *(float4*)&Qs[r * 64 + d4 * 4];
            float4 k0 = *(float4*)&Ks[(lane     ) * KVSTR + d4 * 4];
            float4 k1 = *(float4*)&Ks[(lane + 16) * KVSTR + d4 * 4];
            float4 k2 = *(float4*)&Ks[(lane + 32) * KVSTR + d4 * 4];
            float4 k3 = *(float4*)&Ks[(lane + 48) * KVSTR + d4 * 4];
            a0 += q4.x * k0.x + q4.y * k0.y + q4.z * k0.z + q4.w * k0.w;
            a1 += q4.x * k1.x + q4.y * k1.y + q4.z * k1.z + q4.w * k1.w;
            a2 += q4.x * k2.x + q4.y * k2.y + q4.z * k2.z + q4.w * k2.w;
            a3 += q4.x * k3.x + q4.y * k3.y + q4.z * k3.z + q4.w * k3.w;
        }
        const float invs = 0.125f;  // 1/sqrt(64)
        float s0 = a0 * invs + mrow[kb + lane];
        float s1 = a1 * invs + mrow[kb + lane + 16];
        float s2 = a2 * invs + mrow[kb + lane + 32];
        float s3 = a3 * invs + mrow[kb + lane + 48];
        probs[r * PSTR + kb + lane]      = s0;
        probs[r * PSTR + kb + lane + 16] = s1;
        probs[r * PSTR + kb + lane + 32] = s2;
        probs[r * PSTR + kb + lane + 48] = s3;
        maxv = fmaxf(maxv, fmaxf(fmaxf(s0, s1), fmaxf(s2, s3)));
    }

    // Row max across 16 lanes (lanes of a row are within one warp)
#pragma unroll
    for (int off = 8; off; off >>= 1)
        maxv = fmaxf(maxv, __shfl_xor_sync(0xffffffffu, maxv, off, 16));

    // ---- exp + row sum (each lane touches only elements it wrote) ----
    float sum = 0.f;
#pragma unroll 8
    for (int i = 0; i < 128; i++) {
        int k = lane + 16 * i;
        float e = __expf(probs[r * PSTR + k] - maxv);
        probs[r * PSTR + k] = e;
        sum += e;
    }
#pragma unroll
    for (int off = 8; off; off >>= 1)
        sum += __shfl_xor_sync(0xffffffffu, sum, off, 16);
    const float inv = 1.f / sum;
    if (lane == 0) s_inv[r] = inv;

    // ---- Pass 2: PV. ctx[r][lane*4 .. +3] = sum_k e[k] * V[k][d] ----
    float c0 = 0.f, c1 = 0.f, c2 = 0.f, c3 = 0.f;
    for (int kb = 0; kb < Sc; kb += 64) {
        __syncthreads();
#pragma unroll
        for (int jj = 0; jj < 4; jj++) {
            int id  = tid + jj * 256;
            int row = id >> 4;
            int dq  = (id & 15) * 4;
            float4 v = *(const float4*)(qbase + (size_t)(kb + row) * NQKV + 2 * Dc + h * 64 + dq);
            *(float4*)&Vs[row * KVSTR + dq] = v;
        }
        __syncthreads();
#pragma unroll 8
        for (int k = 0; k < 64; k++) {
            float p = probs[r * PSTR + kb + k];
            float4 v4 = *(float4*)&Vs[k * KVSTR + lane * 4];
            c0 += p * v4.x;
            c1 += p * v4.y;
            c2 += p * v4.z;
            c3 += p * v4.w;
        }
    }

    // context -> g_ctx in [b, s, h*64+d] layout (transpose folded in)
    {
        float4 o = make_float4(c0 * inv, c1 * inv, c2 * inv, c3 * inv);
        *(float4*)(ctx_out + (size_t)(b * Sc + q0 + r) * Dc + h * 64 + lane * 4) = o;
    }
    __syncthreads();

    // Normalized attn_prob write: 16 rows x 2048 = 8192 float4, 32/thread
    float* aout = attn_out + ((size_t)(b * Hc + h) * Sc + q0) * Sc;
#pragma unroll
    for (int jj = 0; jj < 32; jj++) {
        int id = tid + jj * 256;
        int rr = id >> 9;           // 512 float4 per row
        int cc = (id & 511) * 4;
        float iv = s_inv[rr];
        float4 p4 = *(float4*)&probs[rr * PSTR + cc];
        float4 o = make_float4(p4.x * iv, p4.y * iv, p4.z * iv, p4.w * iv);
        *(float4*)(aout + (size_t)rr * Sc + cc) = o;
    }
}

// ---------------------------------------------------------------------------
extern "C" void kernel_launch(void* const* d_in, const int* in_sizes, int n_in,
                              void* d_out, int out_size)
{
    const float* query = (const float*)d_in[0];   // [2,2048,1024]
    const float* mask  = (const float*)d_in[1];   // [2,1,2048,2048]
    const float* w_qkv = (const float*)d_in[2];   // [1024,3072]
    const float* b_qkv = (const float*)d_in[3];   // [3072]
    const float* w_fc  = (const float*)d_in[4];   // [1024,1024]
    const float* b_fc  = (const float*)d_in[5];   // [1024]

    float* out      = (float*)d_out;
    float* ctx_out  = out;                                // [2,2048,1024]
    float* attn_out = out + (size_t)Mc * Dc;              // [2,16,2048,2048]

    float* qkv_ptr = nullptr;
    float* ctx_ptr = nullptr;
    cudaGetSymbolAddress((void**)&qkv_ptr, g_qkv);
    cudaGetSymbolAddress((void**)&ctx_ptr, g_ctx);

    cudaFuncSetAttribute(attn_kernel,
                         cudaFuncAttributeMaxDynamicSharedMemorySize,
                         ATTN_SMEM_BYTES);

    // 1) QKV projection: [4096,1024] @ [1024,3072] + b
    {
        dim3 grid(NQKV / 64, Mc / 128);
        sgemm_bias_kernel<<<grid, 256>>>(query, w_qkv, b_qkv, qkv_ptr,
                                         Mc, NQKV, Dc);
    }
    // 2) Fused attention + softmax + attn_prob write + context
    {
        dim3 grid(Sc / 16, Hc, Bc);
        attn_kernel<<<grid, 256, ATTN_SMEM_BYTES>>>(qkv_ptr, mask, ctx_ptr, attn_out);
    }
    // 3) Output projection: [4096,1024] @ [1024,1024] + b
    {
        dim3 grid(Dc / 64, Mc / 128);
        sgemm_bias_kernel<<<grid, 256>>>(ctx_ptr, w_fc, b_fc, ctx_out,
                                         Mc, Dc, Dc);
    }
}

// round 2
// speedup vs baseline: 2.2830x; 2.2830x over previous
#include <cuda_runtime.h>
#include <cstdint>

// Problem constants
constexpr int Bc = 2, Sc = 2048, Dc = 1024, Hc = 16;
constexpr int Mc = Bc * Sc;        // 4096
constexpr int NQKV = 3 * Dc;       // 3072

// Scratch (device globals; no allocation allowed)
__device__ float g_qkv[Mc * NQKV];   // [4096, 3072]
__device__ float g_ctx[Mc * Dc];     // [4096, 1024]

// ---------------------------------------------------------------------------
// tf32 mma helpers
// ---------------------------------------------------------------------------
__device__ __forceinline__ uint32_t f2tf32(float f) {
    uint32_t u;
    asm("cvt.rna.tf32.f32 %0, %1;" : "=r"(u) : "f"(f));
    return u;
}

__device__ __forceinline__ void mma_tf32(float* c, const uint32_t* a, const uint32_t* b) {
    asm volatile(
        "mma.sync.aligned.m16n8k8.row.col.f32.tf32.tf32.f32 "
        "{%0,%1,%2,%3}, {%4,%5,%6,%7}, {%8,%9}, {%0,%1,%2,%3};\n"
        : "+f"(c[0]), "+f"(c[1]), "+f"(c[2]), "+f"(c[3])
        : "r"(a[0]), "r"(a[1]), "r"(a[2]), "r"(a[3]), "r"(b[0]), "r"(b[1]));
}

// ---------------------------------------------------------------------------
// Tensor-core GEMM + bias: C[M,N] = A[M,K] @ W[K,N] + bias[N]
// BM=256, BN=64, BK=32. 256 threads = 8 warps in 4x2, warp tile 64x32.
// ---------------------------------------------------------------------------
constexpr int GA_STR = 36;  // As row stride (floats)
constexpr int GW_STR = 72;  // Ws row stride (floats)

__global__ __launch_bounds__(256) void gemm_tc(
    const float* __restrict__ A, const float* __restrict__ W,
    const float* __restrict__ bias, float* __restrict__ C,
    int M, int N, int K)
{
    __shared__ __align__(16) float As[256][GA_STR];   // [m][k]
    __shared__ __align__(16) float Ws[32][GW_STR];    // [k][n]

    const int tid    = threadIdx.x;
    const int warp   = tid >> 5;
    const int lane   = tid & 31;
    const int gid    = lane >> 2;     // 0..7
    const int tig    = lane & 3;      // 0..3
    const int warp_m = warp >> 1;     // 0..3
    const int warp_n = warp & 1;      // 0..1
    const int m0 = blockIdx.y * 256;
    const int n0 = blockIdx.x * 64;
    const int mw = warp_m * 64;
    const int nw = warp_n * 32;

    float acc[4][4][4];
#pragma unroll
    for (int i = 0; i < 4; i++)
#pragma unroll
        for (int j = 0; j < 4; j++)
#pragma unroll
            for (int q = 0; q < 4; q++) acc[i][j][q] = 0.f;

    for (int kb = 0; kb < K; kb += 32) {
        // Stage A tile: 256x32 = 2048 float4, 8/thread
#pragma unroll
        for (int j = 0; j < 8; j++) {
            int id   = tid + j * 256;
            int row  = id >> 3;
            int colq = (id & 7) * 4;
            float4 v = *(const float4*)(A + (size_t)(m0 + row) * K + kb + colq);
            *(float4*)&As[row][colq] = v;
        }
        // Stage W tile: 32x64 = 512 float4, 2/thread
#pragma unroll
        for (int j = 0; j < 2; j++) {
            int id   = tid + j * 256;
            int row  = id >> 4;
            int colq = (id & 15) * 4;
            float4 v = *(const float4*)(W + (size_t)(kb + row) * N + n0 + colq);
            *(float4*)&Ws[row][colq] = v;
        }
        __syncthreads();

#pragma unroll
        for (int kk = 0; kk < 4; kk++) {
            const int k8 = kk * 8;
            uint32_t af[4][4];
#pragma unroll
            for (int mt = 0; mt < 4; mt++) {
                int r = mw + mt * 16 + gid;
                af[mt][0] = f2tf32(As[r    ][k8 + tig]);
                af[mt][1] = f2tf32(As[r + 8][k8 + tig]);
                af[mt][2] = f2tf32(As[r    ][k8 + tig + 4]);
                af[mt][3] = f2tf32(As[r + 8][k8 + tig + 4]);
            }
#pragma unroll
            for (int nt = 0; nt < 4; nt++) {
                uint32_t bf[2];
                int c = nw + nt * 8 + gid;
                bf[0] = f2tf32(Ws[k8 + tig    ][c]);
                bf[1] = f2tf32(Ws[k8 + tig + 4][c]);
#pragma unroll
                for (int mt = 0; mt < 4; mt++)
                    mma_tf32(acc[mt][nt], af[mt], bf);
            }
        }
        __syncthreads();
    }

    // Epilogue: bias + store
#pragma unroll
    for (int nt = 0; nt < 4; nt++) {
        int c = n0 + nw + nt * 8 + 2 * tig;
        float b0 = bias[c], b1 = bias[c + 1];
#pragma unroll
        for (int mt = 0; mt < 4; mt++) {
            int r = m0 + mw + mt * 16 + gid;
            float2 o0 = make_float2(acc[mt][nt][0] + b0, acc[mt][nt][1] + b1);
            float2 o1 = make_float2(acc[mt][nt][2] + b0, acc[mt][nt][3] + b1);
            *(float2*)(C + (size_t)r * N + c)       = o0;
            *(float2*)(C + (size_t)(r + 8) * N + c) = o1;
        }
    }
}

// ---------------------------------------------------------------------------
// Fused attention with tf32 mma.
// Block = (b, h, 16-row q tile), 256 threads = 8 warps.
// probs[16][2048] staged in smem across full K range (needed: attn_prob is an
// output). Pass1 QK^T (Q fragments register-resident). Softmax. Pass2 PV with
// warp-per-kstep + cross-warp reduce. Writes normalized attn_prob + context.
// ---------------------------------------------------------------------------
constexpr int PSTR = 2052;   // probs stride: 2052 % 32 == 4 -> conflict-free frags
constexpr int QSTR = 68;
constexpr int KSTR = 72;

constexpr int SM_PROBS = 16 * PSTR;              // 32832
constexpr int SM_QS    = 16 * QSTR;              // 1088
constexpr int SM_KV    = 64 * KSTR;              // 4608
constexpr int SM_RED   = 8 * 16 * 64;            // 8192
constexpr int ATTN_SMEM_BYTES = (SM_PROBS + SM_QS + SM_KV + SM_RED) * 4;

__global__ __launch_bounds__(256) void attn_tc_kernel(
    const float* __restrict__ qkv, const float* __restrict__ mask,
    float* __restrict__ ctx_out, float* __restrict__ attn_out)
{
    extern __shared__ __align__(16) float sm[];
    float* probs = sm;                    // [16][PSTR]
    float* Qs    = probs + SM_PROBS;      // [16][QSTR]
    float* KVs   = Qs + SM_QS;            // [64][KSTR]
    float* red   = KVs + SM_KV;           // [8][16][64]
    __shared__ float s_inv[16];

    const int tid  = threadIdx.x;
    const int warp = tid >> 5;
    const int lane = tid & 31;
    const int gid  = lane >> 2;
    const int tig  = lane & 3;
    const int q0   = blockIdx.x * 16;
    const int h    = blockIdx.y;
    const int b    = blockIdx.z;

    const float* qbase = qkv + (size_t)b * Sc * NQKV;
    const float* mbase = mask + (size_t)b * Sc * Sc;

    // Load Q tile [16 x 64]
    {
        int row  = tid >> 4;
        int colq = (tid & 15) * 4;
        float4 v = *(const float4*)(qbase + (size_t)(q0 + row) * NQKV + h * 64 + colq);
        *(float4*)&Qs[row * QSTR + colq] = v;
    }
    __syncthreads();

    // Q A-fragments, register resident for the whole kernel: 8 ksteps x 4 regs
    uint32_t aq[8][4];
#pragma unroll
    for (int kk = 0; kk < 8; kk++) {
        int d = kk * 8 + tig;
        aq[kk][0] = f2tf32(Qs[gid * QSTR + d]);
        aq[kk][1] = f2tf32(Qs[(gid + 8) * QSTR + d]);
        aq[kk][2] = f2tf32(Qs[gid * QSTR + d + 4]);
        aq[kk][3] = f2tf32(Qs[(gid + 8) * QSTR + d + 4]);
    }

    // ---- Pass 1: scores = QK^T * 0.125 + mask -> probs smem ----
    for (int kb = 0; kb < Sc; kb += 64) {
        __syncthreads();
#pragma unroll
        for (int j = 0; j < 4; j++) {
            int id   = tid + j * 256;
            int row  = id >> 4;
            int colq = (id & 15) * 4;
            float4 v = *(const float4*)(qbase + (size_t)(kb + row) * NQKV + Dc + h * 64 + colq);
            *(float4*)&KVs[row * KSTR + colq] = v;
        }
        __syncthreads();

        // warp's n-tile: kv columns [kb + warp*8, +8)
        float sc[4] = {0.f, 0.f, 0.f, 0.f};
        const int n0w = warp * 8;
#pragma unroll
        for (int kk = 0; kk < 8; kk++) {
            uint32_t bf[2];
            int d = kk * 8 + tig;
            bf[0] = f2tf32(KVs[(n0w + gid) * KSTR + d]);
            bf[1] = f2tf32(KVs[(n0w + gid) * KSTR + d + 4]);
            mma_tf32(sc, aq[kk], bf);
        }
        // epilogue: scale + mask, write to probs
        int c = kb + n0w + 2 * tig;
        float2 m0 = *(const float2*)(mbase + (size_t)(q0 + gid) * Sc + c);
        float2 m1 = *(const float2*)(mbase + (size_t)(q0 + gid + 8) * Sc + c);
        *(float2*)&probs[gid * PSTR + c] =
            make_float2(sc[0] * 0.125f + m0.x, sc[1] * 0.125f + m0.y);
        *(float2*)&probs[(gid + 8) * PSTR + c] =
            make_float2(sc[2] * 0.125f + m1.x, sc[3] * 0.125f + m1.y);
    }
    __syncthreads();

    // ---- Softmax: max, exp, sum (thread = (r, lane16)) ----
    {
        const int r  = tid >> 4;
        const int l  = tid & 15;
        float maxv = -3.0e38f;
#pragma unroll 8
        for (int i = 0; i < 128; i++)
            maxv = fmaxf(maxv, probs[r * PSTR + l + 16 * i]);
#pragma unroll
        for (int off = 8; off; off >>= 1)
            maxv = fmaxf(maxv, __shfl_xor_sync(0xffffffffu, maxv, off, 16));
        float sum = 0.f;
#pragma unroll 8
        for (int i = 0; i < 128; i++) {
            int k = l + 16 * i;
            float e = __expf(probs[r * PSTR + k] - maxv);
            probs[r * PSTR + k] = e;
            sum += e;
        }
#pragma unroll
        for (int off = 8; off; off >>= 1)
            sum += __shfl_xor_sync(0xffffffffu, sum, off, 16);
        if (l == 0) s_inv[r] = 1.f / sum;
    }

    // ---- Pass 2: context = probs @ V. Warp owns kstep (warp*8 kv rows per
    // staged 64-row chunk), covers all 8 d-tiles -> partial [16][64] ----
    float co[8][4];
#pragma unroll
    for (int nt = 0; nt < 8; nt++)
#pragma unroll
        for (int q = 0; q < 4; q++) co[nt][q] = 0.f;

    for (int kb = 0; kb < Sc; kb += 64) {
        __syncthreads();
#pragma unroll
        for (int j = 0; j < 4; j++) {
            int id   = tid + j * 256;
            int row  = id >> 4;
            int colq = (id & 15) * 4;
            float4 v = *(const float4*)(qbase + (size_t)(kb + row) * NQKV + 2 * Dc + h * 64 + colq);
            *(float4*)&KVs[row * KSTR + colq] = v;
        }
        __syncthreads();

        const int kvr = warp * 8;  // warp's kstep within chunk
        uint32_t ap[4];
        ap[0] = f2tf32(probs[gid * PSTR + kb + kvr + tig]);
        ap[1] = f2tf32(probs[(gid + 8) * PSTR + kb + kvr + tig]);
        ap[2] = f2tf32(probs[gid * PSTR + kb + kvr + tig + 4]);
        ap[3] = f2tf32(probs[(gid + 8) * PSTR + kb + kvr + tig + 4]);
#pragma unroll
        for (int nt = 0; nt < 8; nt++) {
            uint32_t bf[2];
            int d = nt * 8 + gid;
            bf[0] = f2tf32(KVs[(kvr + tig) * KSTR + d]);
            bf[1] = f2tf32(KVs[(kvr + tig + 4) * KSTR + d]);
            mma_tf32(co[nt], ap, bf);
        }
    }

    // write warp partials, reduce across warps, scale by inv, store context
#pragma unroll
    for (int nt = 0; nt < 8; nt++) {
        int d = nt * 8 + 2 * tig;
        *(float2*)&red[(warp * 16 + gid) * 64 + d]     = make_float2(co[nt][0], co[nt][1]);
        *(float2*)&red[(warp * 16 + gid + 8) * 64 + d] = make_float2(co[nt][2], co[nt][3]);
    }
    __syncthreads();
#pragma unroll
    for (int j = 0; j < 4; j++) {
        int idx = tid + j * 256;
        int row = idx >> 6;
        int d   = idx & 63;
        float s = 0.f;
#pragma unroll
        for (int w = 0; w < 8; w++) s += red[(w * 16 + row) * 64 + d];
        ctx_out[(size_t)(b * Sc + q0 + row) * Dc + h * 64 + d] = s * s_inv[row];
    }

    // normalized attn_prob write: 16 x 2048 = 8192 float4, 32/thread
    float* aout = attn_out + ((size_t)(b * Hc + h) * Sc + q0) * Sc;
#pragma unroll
    for (int j = 0; j < 32; j++) {
        int id = tid + j * 256;
        int rr = id >> 9;
        int cc = (id & 511) * 4;
        float iv = s_inv[rr];
        float4 p4 = *(float4*)&probs[rr * PSTR + cc];
        float4 o = make_float4(p4.x * iv, p4.y * iv, p4.z * iv, p4.w * iv);
        *(float4*)(aout + (size_t)rr * Sc + cc) = o;
    }
}

// ---------------------------------------------------------------------------
extern "C" void kernel_launch(void* const* d_in, const int* in_sizes, int n_in,
                              void* d_out, int out_size)
{
    const float* query = (const float*)d_in[0];   // [2,2048,1024]
    const float* mask  = (const float*)d_in[1];   // [2,1,2048,2048]
    const float* w_qkv = (const float*)d_in[2];   // [1024,3072]
    const float* b_qkv = (const float*)d_in[3];   // [3072]
    const float* w_fc  = (const float*)d_in[4];   // [1024,1024]
    const float* b_fc  = (const float*)d_in[5];   // [1024]

    float* out      = (float*)d_out;
    float* ctx_out  = out;                         // [2,2048,1024]
    float* attn_out = out + (size_t)Mc * Dc;       // [2,16,2048,2048]

    float* qkv_ptr = nullptr;
    float* ctx_ptr = nullptr;
    cudaGetSymbolAddress((void**)&qkv_ptr, g_qkv);
    cudaGetSymbolAddress((void**)&ctx_ptr, g_ctx);

    cudaFuncSetAttribute(attn_tc_kernel,
                         cudaFuncAttributeMaxDynamicSharedMemorySize,
                         ATTN_SMEM_BYTES);

    // 1) QKV projection
    {
        dim3 grid(NQKV / 64, Mc / 256);
        gemm_tc<<<grid, 256>>>(query, w_qkv, b_qkv, qkv_ptr, Mc, NQKV, Dc);
    }
    // 2) Fused attention
    {
        dim3 grid(Sc / 16, Hc, Bc);
        attn_tc_kernel<<<grid, 256, ATTN_SMEM_BYTES>>>(qkv_ptr, mask, ctx_ptr, attn_out);
    }
    // 3) Output projection
    {
        dim3 grid(Dc / 64, Mc / 256);
        gemm_tc<<<grid, 256>>>(ctx_ptr, w_fc, b_fc, ctx_out, Mc, Dc, Dc);
    }
}

// round 3
// speedup vs baseline: 3.9686x; 1.7383x over previous
#include <cuda_runtime.h>
#include <cstdint>

// Problem constants
constexpr int Bc = 2, Sc = 2048, Dc = 1024, Hc = 16;
constexpr int Mc = Bc * Sc;        // 4096
constexpr int NQKV = 3 * Dc;       // 3072

// Scratch (device globals; no allocation allowed)
__device__ float g_qkv[Mc * NQKV];   // [4096, 3072]
__device__ float g_ctx[Mc * Dc];     // [4096, 1024]

// ---------------------------------------------------------------------------
// helpers
// ---------------------------------------------------------------------------
__device__ __forceinline__ uint32_t f2tf32(float f) {
    uint32_t u;
    asm("cvt.rna.tf32.f32 %0, %1;" : "=r"(u) : "f"(f));
    return u;
}

__device__ __forceinline__ void mma_tf32(float* c, const uint32_t* a, const uint32_t* b) {
    asm volatile(
        "mma.sync.aligned.m16n8k8.row.col.f32.tf32.tf32.f32 "
        "{%0,%1,%2,%3}, {%4,%5,%6,%7}, {%8,%9}, {%0,%1,%2,%3};\n"
        : "+f"(c[0]), "+f"(c[1]), "+f"(c[2]), "+f"(c[3])
        : "r"(a[0]), "r"(a[1]), "r"(a[2]), "r"(a[3]), "r"(b[0]), "r"(b[1]));
}

__device__ __forceinline__ void cp16(void* smem, const void* gmem) {
    uint32_t s = (uint32_t)__cvta_generic_to_shared(smem);
    asm volatile("cp.async.ca.shared.global [%0], [%1], 16;" :: "r"(s), "l"(gmem));
}
__device__ __forceinline__ void cp_commit() { asm volatile("cp.async.commit_group;"); }
__device__ __forceinline__ void cp_wait1()  { asm volatile("cp.async.wait_group 1;"); }

// ---------------------------------------------------------------------------
// Tensor-core GEMM + bias, 2-stage cp.async pipeline.
// BM=256, BN=64, BK=32. 256 threads = 8 warps (4x2), warp tile 64x32.
// ---------------------------------------------------------------------------
constexpr int GA_STR = 36;
constexpr int GW_STR = 72;
constexpr int GEMM_SMEM_BYTES = (2 * 256 * GA_STR + 2 * 32 * GW_STR) * 4;  // 92160

__global__ __launch_bounds__(256) void gemm_tc(
    const float* __restrict__ A, const float* __restrict__ W,
    const float* __restrict__ bias, float* __restrict__ C,
    int M, int N, int K)
{
    extern __shared__ __align__(16) float gsm[];
    float* As = gsm;                       // [2][256][GA_STR]
    float* Ws = gsm + 2 * 256 * GA_STR;    // [2][32][GW_STR]

    const int tid    = threadIdx.x;
    const int warp   = tid >> 5;
    const int lane   = tid & 31;
    const int gid    = lane >> 2;
    const int tig    = lane & 3;
    const int warp_m = warp >> 1;
    const int warp_n = warp & 1;
    const int m0 = blockIdx.y * 256;
    const int n0 = blockIdx.x * 64;
    const int mw = warp_m * 64;
    const int nw = warp_n * 32;

    // per-thread staging coordinates
    const int arow  = tid >> 3;          // 0..255 (two halves via +0 only; 8 f4/thread below)
    const int acolq = (tid & 7) * 4;
    const int wrow  = tid >> 4;
    const int wcolq = (tid & 15) * 4;

    auto load_stage = [&](int s, int kb) {
        float* as = As + s * 256 * GA_STR;
        float* ws = Ws + s * 32 * GW_STR;
#pragma unroll
        for (int j = 0; j < 8; j++) {
            int id   = tid + j * 256;
            int row  = id >> 3;
            int colq = (id & 7) * 4;
            cp16(&as[row * GA_STR + colq], A + (size_t)(m0 + row) * K + kb + colq);
        }
#pragma unroll
        for (int j = 0; j < 2; j++) {
            int id   = tid + j * 256;
            int row  = id >> 4;
            int colq = (id & 15) * 4;
            cp16(&ws[row * GW_STR + colq], W + (size_t)(kb + row) * N + n0 + colq);
        }
    };

    float acc[4][4][4];
#pragma unroll
    for (int i = 0; i < 4; i++)
#pragma unroll
        for (int j = 0; j < 4; j++)
#pragma unroll
            for (int q = 0; q < 4; q++) acc[i][j][q] = 0.f;

    const int nK = K / 32;
    load_stage(0, 0);
    cp_commit();

    for (int kbi = 0; kbi < nK; kbi++) {
        const int s = kbi & 1;
        if (kbi + 1 < nK) load_stage(s ^ 1, (kbi + 1) * 32);
        cp_commit();
        cp_wait1();
        __syncthreads();

        const float* as = As + s * 256 * GA_STR;
        const float* ws = Ws + s * 32 * GW_STR;
#pragma unroll
        for (int kk = 0; kk < 4; kk++) {
            const int k8 = kk * 8;
            uint32_t af[4][4];
#pragma unroll
            for (int mt = 0; mt < 4; mt++) {
                int r = mw + mt * 16 + gid;
                af[mt][0] = f2tf32(as[r * GA_STR + k8 + tig]);
                af[mt][1] = f2tf32(as[(r + 8) * GA_STR + k8 + tig]);
                af[mt][2] = f2tf32(as[r * GA_STR + k8 + tig + 4]);
                af[mt][3] = f2tf32(as[(r + 8) * GA_STR + k8 + tig + 4]);
            }
#pragma unroll
            for (int nt = 0; nt < 4; nt++) {
                uint32_t bf[2];
                int c = nw + nt * 8 + gid;
                bf[0] = f2tf32(ws[(k8 + tig) * GW_STR + c]);
                bf[1] = f2tf32(ws[(k8 + tig + 4) * GW_STR + c]);
#pragma unroll
                for (int mt = 0; mt < 4; mt++)
                    mma_tf32(acc[mt][nt], af[mt], bf);
            }
        }
        __syncthreads();
    }

#pragma unroll
    for (int nt = 0; nt < 4; nt++) {
        int c = n0 + nw + nt * 8 + 2 * tig;
        float b0 = bias[c], b1 = bias[c + 1];
#pragma unroll
        for (int mt = 0; mt < 4; mt++) {
            int r = m0 + mw + mt * 16 + gid;
            *(float2*)(C + (size_t)r * N + c) =
                make_float2(acc[mt][nt][0] + b0, acc[mt][nt][1] + b1);
            *(float2*)(C + (size_t)(r + 8) * N + c) =
                make_float2(acc[mt][nt][2] + b0, acc[mt][nt][3] + b1);
        }
    }
}

// ---------------------------------------------------------------------------
// Fused attention, recompute strategy.
// Block = (b, h, 128-row q tile), 256 threads = 8 warps, each warp 16 q-rows.
// Pass A: QK^T, online (max,sum) in registers only.
// Pass B: recompute QK^T, p = exp(s-m)*invZ -> smem chunk -> PV mma + coalesced
//         global write of attn_prob. Context accumulated in registers.
// ---------------------------------------------------------------------------
constexpr int QSTR = 68;   // Q / probs stride  (68 % 32 == 4 -> conflict-free frags)
constexpr int KSTR = 68;   // K tile stride
constexpr int VSTR = 72;   // V tile stride     (72 % 32 == 8 -> conflict-free frags)

constexpr int SM_QS = 128 * QSTR;   // aliased: Q tile, then prob chunk [128][68]
constexpr int SM_KS = 64 * KSTR;
constexpr int SM_VS = 64 * VSTR;
constexpr int ATTN_SMEM_BYTES = (SM_QS + SM_KS + SM_VS) * 4;  // 70,656 B

__global__ __launch_bounds__(256, 2) void attn_tc_kernel(
    const float* __restrict__ qkv, const float* __restrict__ mask,
    float* __restrict__ ctx_out, float* __restrict__ attn_out)
{
    extern __shared__ __align__(16) float sm[];
    float* Qs    = sm;             // [128][QSTR] ; becomes probs in pass B
    float* probs = sm;
    float* Ks    = sm + SM_QS;     // [64][KSTR]
    float* Vs    = Ks + SM_KS;     // [64][VSTR]

    const int tid  = threadIdx.x;
    const int warp = tid >> 5;
    const int lane = tid & 31;
    const int gid  = lane >> 2;
    const int tig  = lane & 3;
    const int mw   = warp * 16;
    const int q0   = blockIdx.x * 128;
    const int h    = blockIdx.y;
    const int b    = blockIdx.z;

    const float* qbase = qkv + (size_t)b * Sc * NQKV;
    const float* mrow0 = mask + (size_t)b * Sc * Sc + (size_t)(q0 + mw + gid) * Sc;
    const float* mrow1 = mrow0 + 8 * Sc;

    // ---- stage Q tile [128 x 64], extract register-resident A fragments ----
#pragma unroll
    for (int j = 0; j < 8; j++) {
        int id   = tid + j * 256;
        int row  = id >> 4;
        int colq = (id & 15) * 4;
        float4 v = *(const float4*)(qbase + (size_t)(q0 + row) * NQKV + h * 64 + colq);
        *(float4*)&Qs[row * QSTR + colq] = v;
    }
    __syncthreads();

    uint32_t aq[8][4];
#pragma unroll
    for (int kk = 0; kk < 8; kk++) {
        int d = kk * 8 + tig;
        aq[kk][0] = f2tf32(Qs[(mw + gid) * QSTR + d]);
        aq[kk][1] = f2tf32(Qs[(mw + gid + 8) * QSTR + d]);
        aq[kk][2] = f2tf32(Qs[(mw + gid) * QSTR + d + 4]);
        aq[kk][3] = f2tf32(Qs[(mw + gid + 8) * QSTR + d + 4]);
    }
    __syncthreads();   // Qs free -> reused as probs in pass B

    // ---- Pass A: online (m, l) ----
    float m0 = -3.0e38f, m1 = -3.0e38f, l0 = 0.f, l1 = 0.f;

    for (int kb = 0; kb < Sc; kb += 64) {
        __syncthreads();
#pragma unroll
        for (int j = 0; j < 4; j++) {
            int id   = tid + j * 256;
            int row  = id >> 4;
            int colq = (id & 15) * 4;
            float4 v = *(const float4*)(qbase + (size_t)(kb + row) * NQKV + Dc + h * 64 + colq);
            *(float4*)&Ks[row * KSTR + colq] = v;
        }
        __syncthreads();

#pragma unroll
        for (int nt = 0; nt < 8; nt++) {
            float s[4] = {0.f, 0.f, 0.f, 0.f};
#pragma unroll
            for (int kk = 0; kk < 8; kk++) {
                uint32_t bf[2];
                int n = nt * 8 + gid;
                int d = kk * 8 + tig;
                bf[0] = f2tf32(Ks[n * KSTR + d]);
                bf[1] = f2tf32(Ks[n * KSTR + d + 4]);
                mma_tf32(s, aq[kk], bf);
            }
            int c = kb + nt * 8 + 2 * tig;
            float2 mk0 = *(const float2*)(mrow0 + c);
            float2 mk1 = *(const float2*)(mrow1 + c);
            float s0 = s[0] * 0.125f + mk0.x;
            float s1 = s[1] * 0.125f + mk0.y;
            float s2 = s[2] * 0.125f + mk1.x;
            float s3 = s[3] * 0.125f + mk1.y;

            float mn0 = fmaxf(m0, fmaxf(s0, s1));
            if (mn0 != m0) l0 *= __expf(m0 - mn0);
            l0 += __expf(s0 - mn0) + __expf(s1 - mn0);
            m0 = mn0;

            float mn1 = fmaxf(m1, fmaxf(s2, s3));
            if (mn1 != m1) l1 *= __expf(m1 - mn1);
            l1 += __expf(s2 - mn1) + __expf(s3 - mn1);
            m1 = mn1;
        }
    }

    // combine (m,l) across the 4 tig lanes of each row
#pragma unroll
    for (int off = 1; off < 4; off <<= 1) {
        float mo = __shfl_xor_sync(0xffffffffu, m0, off, 4);
        float lo = __shfl_xor_sync(0xffffffffu, l0, off, 4);
        float mn = fmaxf(m0, mo);
        l0 = l0 * __expf(m0 - mn) + lo * __expf(mo - mn);
        m0 = mn;
        mo = __shfl_xor_sync(0xffffffffu, m1, off, 4);
        lo = __shfl_xor_sync(0xffffffffu, l1, off, 4);
        mn = fmaxf(m1, mo);
        l1 = l1 * __expf(m1 - mn) + lo * __expf(mo - mn);
        m1 = mn;
    }
    const float iz0 = 1.f / l0;
    const float iz1 = 1.f / l1;

    // ---- Pass B: recompute, normalize, PV, stream attn_prob ----
    float ctx[8][4];
#pragma unroll
    for (int dt = 0; dt < 8; dt++)
#pragma unroll
        for (int q = 0; q < 4; q++) ctx[dt][q] = 0.f;

    float* aout = attn_out + ((size_t)(b * Hc + h) * Sc + q0) * Sc;

    for (int kb = 0; kb < Sc; kb += 64) {
        __syncthreads();
#pragma unroll
        for (int j = 0; j < 4; j++) {
            int id   = tid + j * 256;
            int row  = id >> 4;
            int colq = (id & 15) * 4;
            float4 kv = *(const float4*)(qbase + (size_t)(kb + row) * NQKV + Dc + h * 64 + colq);
            *(float4*)&Ks[row * KSTR + colq] = kv;
            float4 vv = *(const float4*)(qbase + (size_t)(kb + row) * NQKV + 2 * Dc + h * 64 + colq);
            *(float4*)&Vs[row * VSTR + colq] = vv;
        }
        __syncthreads();

#pragma unroll
        for (int nt = 0; nt < 8; nt++) {
            float s[4] = {0.f, 0.f, 0.f, 0.f};
#pragma unroll
            for (int kk = 0; kk < 8; kk++) {
                uint32_t bf[2];
                int n = nt * 8 + gid;
                int d = kk * 8 + tig;
                bf[0] = f2tf32(Ks[n * KSTR + d]);
                bf[1] = f2tf32(Ks[n * KSTR + d + 4]);
                mma_tf32(s, aq[kk], bf);
            }
            int cl = nt * 8 + 2 * tig;
            int c  = kb + cl;
            float2 mk0 = *(const float2*)(mrow0 + c);
            float2 mk1 = *(const float2*)(mrow1 + c);
            float p0 = __expf(s[0] * 0.125f + mk0.x - m0) * iz0;
            float p1 = __expf(s[1] * 0.125f + mk0.y - m0) * iz0;
            float p2 = __expf(s[2] * 0.125f + mk1.x - m1) * iz1;
            float p3 = __expf(s[3] * 0.125f + mk1.y - m1) * iz1;
            *(float2*)&probs[(mw + gid) * QSTR + cl]     = make_float2(p0, p1);
            *(float2*)&probs[(mw + gid + 8) * QSTR + cl] = make_float2(p2, p3);
        }
        __syncthreads();

        // PV: ctx += P(16xk) @ V(kx64), warp's own 16 q-rows
#pragma unroll
        for (int kk = 0; kk < 8; kk++) {
            uint32_t ap[4];
            int kt = kk * 8 + tig;
            ap[0] = f2tf32(probs[(mw + gid) * QSTR + kt]);
            ap[1] = f2tf32(probs[(mw + gid + 8) * QSTR + kt]);
            ap[2] = f2tf32(probs[(mw + gid) * QSTR + kt + 4]);
            ap[3] = f2tf32(probs[(mw + gid + 8) * QSTR + kt + 4]);
#pragma unroll
            for (int dt = 0; dt < 8; dt++) {
                uint32_t bf[2];
                int d = dt * 8 + gid;
                bf[0] = f2tf32(Vs[kt * VSTR + d]);
                bf[1] = f2tf32(Vs[(kt + 4) * VSTR + d]);
                mma_tf32(ctx[dt], ap, bf);
            }
        }

        // stream normalized probs chunk to global (coalesced float4)
#pragma unroll
        for (int j = 0; j < 8; j++) {
            int id   = tid + j * 256;
            int row  = id >> 4;
            int colq = (id & 15) * 4;
            float4 p4 = *(float4*)&probs[row * QSTR + colq];
            *(float4*)(aout + (size_t)row * Sc + kb + colq) = p4;
        }
    }

    // ---- context write ----
#pragma unroll
    for (int dt = 0; dt < 8; dt++) {
        int d = dt * 8 + 2 * tig;
        int r = q0 + mw + gid;
        *(float2*)(ctx_out + (size_t)(b * Sc + r) * Dc + h * 64 + d) =
            make_float2(ctx[dt][0], ctx[dt][1]);
        *(float2*)(ctx_out + (size_t)(b * Sc + r + 8) * Dc + h * 64 + d) =
            make_float2(ctx[dt][2], ctx[dt][3]);
    }
}

// ---------------------------------------------------------------------------
extern "C" void kernel_launch(void* const* d_in, const int* in_sizes, int n_in,
                              void* d_out, int out_size)
{
    const float* query = (const float*)d_in[0];
    const float* mask  = (const float*)d_in[1];
    const float* w_qkv = (const float*)d_in[2];
    const float* b_qkv = (const float*)d_in[3];
    const float* w_fc  = (const float*)d_in[4];
    const float* b_fc  = (const float*)d_in[5];

    float* out      = (float*)d_out;
    float* ctx_out  = out;                         // [2,2048,1024]
    float* attn_out = out + (size_t)Mc * Dc;       // [2,16,2048,2048]

    float* qkv_ptr = nullptr;
    float* ctx_ptr = nullptr;
    cudaGetSymbolAddress((void**)&qkv_ptr, g_qkv);
    cudaGetSymbolAddress((void**)&ctx_ptr, g_ctx);

    cudaFuncSetAttribute(gemm_tc,
                         cudaFuncAttributeMaxDynamicSharedMemorySize,
                         GEMM_SMEM_BYTES);
    cudaFuncSetAttribute(attn_tc_kernel,
                         cudaFuncAttributeMaxDynamicSharedMemorySize,
                         ATTN_SMEM_BYTES);

    // 1) QKV projection
    {
        dim3 grid(NQKV / 64, Mc / 256);
        gemm_tc<<<grid, 256, GEMM_SMEM_BYTES>>>(query, w_qkv, b_qkv, qkv_ptr, Mc, NQKV, Dc);
    }
    // 2) Fused attention
    {
        dim3 grid(Sc / 128, Hc, Bc);
        attn_tc_kernel<<<grid, 256, ATTN_SMEM_BYTES>>>(qkv_ptr, mask, ctx_ptr, attn_out);
    }
    // 3) Output projection
    {
        dim3 grid(Dc / 64, Mc / 256);
        gemm_tc<<<grid, 256, GEMM_SMEM_BYTES>>>(ctx_ptr, w_fc, b_fc, ctx_out, Mc, Dc, Dc);
    }
}